// round 15
// baseline (speedup 1.0000x reference)
#include <cuda_runtime.h>

#define CDIM   256
#define CDIM4  64          // CDIM/4
#define NV_MAX 20000
#define ME_MAX 4000
#define NNZ_MAX 160000
#define CAP_E  192         // padded CSR capacity per edge   (mean 40)
#define CAP_V  64          // padded CSR capacity per vertex (mean 8)
#define WN_MAX ((NV_MAX + 31) / 32)   // 625 words for the per-edge vertex bitmap
#define WPB    8           // warps per block in the gather kernels

// -------------------- static device scratch --------------------
__device__ float4 d_Y4[ME_MAX * CDIM4];    // edge-aggregated X, pre-scaled by sE  [4 MB]
__device__ float4 d_XeP4[ME_MAX * CDIM4];  // projected edge features              [4 MB]
__device__ int   d_cur[ME_MAX + NV_MAX];   // atomic cursors: [0,Me) = E, [Me,Me+Nv) = V
__device__ int   d_csrEp[ME_MAX * CAP_E];  // padded: vertices of edge e
__device__ int   d_csrVp[NV_MAX * CAP_V];  // padded: edges of vertex v

// -------------------- fused padded CSR fill (E and V in one pass) --------------------
__global__ void fill_kernel(const int4* __restrict__ vertex4, const int4* __restrict__ edges4,
                            int nnz4, int Me)
{
    int k = blockIdx.x * blockDim.x + threadIdx.x;
    if (k >= nnz4) return;
    int4 v = vertex4[k];
    int4 e = edges4[k];
    int p;
    p = atomicAdd(&d_cur[e.x], 1); if (p < CAP_E) d_csrEp[e.x * CAP_E + p] = v.x;
    p = atomicAdd(&d_cur[e.y], 1); if (p < CAP_E) d_csrEp[e.y * CAP_E + p] = v.y;
    p = atomicAdd(&d_cur[e.z], 1); if (p < CAP_E) d_csrEp[e.z * CAP_E + p] = v.z;
    p = atomicAdd(&d_cur[e.w], 1); if (p < CAP_E) d_csrEp[e.w * CAP_E + p] = v.w;
    p = atomicAdd(&d_cur[Me + v.x], 1); if (p < CAP_V) d_csrVp[v.x * CAP_V + p] = e.x;
    p = atomicAdd(&d_cur[Me + v.y], 1); if (p < CAP_V) d_csrVp[v.y * CAP_V + p] = e.y;
    p = atomicAdd(&d_cur[Me + v.z], 1); if (p < CAP_V) d_csrVp[v.z * CAP_V + p] = e.z;
    p = atomicAdd(&d_cur[Me + v.w], 1); if (p < CAP_V) d_csrVp[v.w * CAP_V + p] = e.w;
}

// ---- vertex -> edge gather, WARP per edge (8 warps/block) + per-warp bitmap dedup ------
__global__ __launch_bounds__(32 * WPB)
void edge_gather_kernel(const float4* __restrict__ X4, int wn, int Me)
{
    __shared__ unsigned bm[WPB][WN_MAX];    // 8 x 2.5 KB = 20 KB

    int warpInBlk = threadIdx.x >> 5;
    int lane = threadIdx.x & 31;
    int e = blockIdx.x * WPB + warpInBlk;
    if (e >= Me) return;                    // whole warp exits together

    int cnt = d_cur[e];
    int n = min(cnt, CAP_E);
    int base = e * CAP_E;

    unsigned* mybm = bm[warpInBlk];
    for (int i = lane; i < wn; i += 32) mybm[i] = 0u;
    __syncwarp();

    // pass 1: distinct count via per-warp smem bitmap
    int mine = 0;
    for (int i = lane; i < n; i += 32) {
        int v = d_csrEp[base + i];
        unsigned bit = 1u << (v & 31);
        unsigned old = atomicOr(&mybm[v >> 5], bit);
        if (!(old & bit)) mine++;
    }
    int distinct = __reduce_add_sync(0xffffffffu, mine);
    float s = rsqrtf((float)distinct) / ((float)cnt + 1e-8f);

    // pass 2: gather-sum X rows; lane handles float4 columns lane and lane+32
    float4 accA = make_float4(0.f, 0.f, 0.f, 0.f);
    float4 accB = make_float4(0.f, 0.f, 0.f, 0.f);
    int i = 0;
    for (; i + 2 <= n; i += 2) {
        int v0 = d_csrEp[base + i + 0];
        int v1 = d_csrEp[base + i + 1];
        const float4* r0 = &X4[(long)v0 * CDIM4];
        const float4* r1 = &X4[(long)v1 * CDIM4];
        float4 a0 = r0[lane],      a1 = r1[lane];
        float4 b0 = r0[lane + 32], b1 = r1[lane + 32];
        accA.x += a0.x + a1.x; accA.y += a0.y + a1.y;
        accA.z += a0.z + a1.z; accA.w += a0.w + a1.w;
        accB.x += b0.x + b1.x; accB.y += b0.y + b1.y;
        accB.z += b0.z + b1.z; accB.w += b0.w + b1.w;
    }
    for (; i < n; i++) {
        const float4* r = &X4[(long)d_csrEp[base + i] * CDIM4];
        float4 a = r[lane], b = r[lane + 32];
        accA.x += a.x; accA.y += a.y; accA.z += a.z; accA.w += a.w;
        accB.x += b.x; accB.y += b.y; accB.z += b.z; accB.w += b.w;
    }
    d_Y4[(long)e * CDIM4 + lane]      = make_float4(accA.x*s, accA.y*s, accA.z*s, accA.w*s);
    d_Y4[(long)e * CDIM4 + lane + 32] = make_float4(accB.x*s, accB.y*s, accB.z*s, accB.w*s);
}

// -------------------- SGEMM: XeP = Y @ W^T  (M=4000, K=256), double-buffered ------------
#define BM 128
#define BN 64
#define BK 16

__global__ __launch_bounds__(256)
void sgemm_kernel(const float* __restrict__ A, const float* __restrict__ B,
                  float* __restrict__ Cmat, int Nrows)
{
    __shared__ float As[2][BK][BM];
    __shared__ float Bs[2][BK][BN];

    const int tid = threadIdx.x;
    const int brow0 = blockIdx.x * BM;
    const int bcol0 = blockIdx.y * BN;
    const int tx = tid & 15;
    const int ty = tid >> 4;

    float4 c0 = make_float4(0.f,0.f,0.f,0.f);
    float4 c1 = c0, c2 = c0, c3 = c0, c4 = c0, c5 = c0, c6 = c0, c7 = c0;

    const int a0row = tid >> 2;
    const int a1row = a0row + 64;
    const int lk4   = (tid & 3) * 4;
    const int ga0 = brow0 + a0row;
    const int ga1 = brow0 + a1row;
    const bool av0 = (ga0 < Nrows);
    const bool av1 = (ga1 < Nrows);
    const int gb  = bcol0 + a0row;
    const float4 z4 = make_float4(0.f,0.f,0.f,0.f);

    {
        float4 va0 = av0 ? *(const float4*)&A[(long)ga0 * CDIM + lk4] : z4;
        float4 va1 = av1 ? *(const float4*)&A[(long)ga1 * CDIM + lk4] : z4;
        float4 vb  = *(const float4*)&B[(long)gb * CDIM + lk4];
        As[0][lk4 + 0][a0row] = va0.x;  As[0][lk4 + 1][a0row] = va0.y;
        As[0][lk4 + 2][a0row] = va0.z;  As[0][lk4 + 3][a0row] = va0.w;
        As[0][lk4 + 0][a1row] = va1.x;  As[0][lk4 + 1][a1row] = va1.y;
        As[0][lk4 + 2][a1row] = va1.z;  As[0][lk4 + 3][a1row] = va1.w;
        Bs[0][lk4 + 0][a0row] = vb.x;   Bs[0][lk4 + 1][a0row] = vb.y;
        Bs[0][lk4 + 2][a0row] = vb.z;   Bs[0][lk4 + 3][a0row] = vb.w;
    }
    __syncthreads();

    int buf = 0;
#pragma unroll 1
    for (int t = 0; t < CDIM / BK; t++) {
        float4 na0, na1, nb;
        const bool more = (t < CDIM / BK - 1);
        if (more) {
            int kt = (t + 1) * BK;
            na0 = av0 ? *(const float4*)&A[(long)ga0 * CDIM + kt + lk4] : z4;
            na1 = av1 ? *(const float4*)&A[(long)ga1 * CDIM + kt + lk4] : z4;
            nb  = *(const float4*)&B[(long)gb * CDIM + kt + lk4];
        }
#pragma unroll
        for (int k = 0; k < BK; k++) {
            float4 af0 = *(const float4*)&As[buf][k][ty * 8];
            float4 af1 = *(const float4*)&As[buf][k][ty * 8 + 4];
            float4 bf  = *(const float4*)&Bs[buf][k][tx * 4];
            c0.x += af0.x * bf.x; c0.y += af0.x * bf.y; c0.z += af0.x * bf.z; c0.w += af0.x * bf.w;
            c1.x += af0.y * bf.x; c1.y += af0.y * bf.y; c1.z += af0.y * bf.z; c1.w += af0.y * bf.w;
            c2.x += af0.z * bf.x; c2.y += af0.z * bf.y; c2.z += af0.z * bf.z; c2.w += af0.z * bf.w;
            c3.x += af0.w * bf.x; c3.y += af0.w * bf.y; c3.z += af0.w * bf.z; c3.w += af0.w * bf.w;
            c4.x += af1.x * bf.x; c4.y += af1.x * bf.y; c4.z += af1.x * bf.z; c4.w += af1.x * bf.w;
            c5.x += af1.y * bf.x; c5.y += af1.y * bf.y; c5.z += af1.y * bf.z; c5.w += af1.y * bf.w;
            c6.x += af1.z * bf.x; c6.y += af1.z * bf.y; c6.z += af1.z * bf.z; c6.w += af1.z * bf.w;
            c7.x += af1.w * bf.x; c7.y += af1.w * bf.y; c7.z += af1.w * bf.z; c7.w += af1.w * bf.w;
        }
        if (more) {
            int nbuf = buf ^ 1;
            As[nbuf][lk4 + 0][a0row] = na0.x;  As[nbuf][lk4 + 1][a0row] = na0.y;
            As[nbuf][lk4 + 2][a0row] = na0.z;  As[nbuf][lk4 + 3][a0row] = na0.w;
            As[nbuf][lk4 + 0][a1row] = na1.x;  As[nbuf][lk4 + 1][a1row] = na1.y;
            As[nbuf][lk4 + 2][a1row] = na1.z;  As[nbuf][lk4 + 3][a1row] = na1.w;
            Bs[nbuf][lk4 + 0][a0row] = nb.x;   Bs[nbuf][lk4 + 1][a0row] = nb.y;
            Bs[nbuf][lk4 + 2][a0row] = nb.z;   Bs[nbuf][lk4 + 3][a0row] = nb.w;
        }
        __syncthreads();
        buf ^= 1;
    }

    const int orow = brow0 + ty * 8;
    const int ocol = bcol0 + tx * 4;
    if (orow + 0 < Nrows) *(float4*)&Cmat[(long)(orow + 0) * CDIM + ocol] = c0;
    if (orow + 1 < Nrows) *(float4*)&Cmat[(long)(orow + 1) * CDIM + ocol] = c1;
    if (orow + 2 < Nrows) *(float4*)&Cmat[(long)(orow + 2) * CDIM + ocol] = c2;
    if (orow + 3 < Nrows) *(float4*)&Cmat[(long)(orow + 3) * CDIM + ocol] = c3;
    if (orow + 4 < Nrows) *(float4*)&Cmat[(long)(orow + 4) * CDIM + ocol] = c4;
    if (orow + 5 < Nrows) *(float4*)&Cmat[(long)(orow + 5) * CDIM + ocol] = c5;
    if (orow + 6 < Nrows) *(float4*)&Cmat[(long)(orow + 6) * CDIM + ocol] = c6;
    if (orow + 7 < Nrows) *(float4*)&Cmat[(long)(orow + 7) * CDIM + ocol] = c7;
}

// ---- edge -> vertex gather, WARP per vertex (8 warps/block), warp-local dedup ----------
__global__ __launch_bounds__(32 * WPB)
void vertex_gather_kernel(float4* __restrict__ out4, int Me, int Nv)
{
    int warpInBlk = threadIdx.x >> 5;
    int lane = threadIdx.x & 31;
    int v = blockIdx.x * WPB + warpInBlk;
    if (v >= Nv) return;                    // whole warp exits together

    int cnt = d_cur[Me + v];
    int n = min(cnt, CAP_V);
    int base = v * CAP_V;

    // dedup: lane-strided O(n^2) over L2-hot indices (n ~ 8)
    int mine = 0;
    for (int i = lane; i < n; i += 32) {
        int val = d_csrVp[base + i];
        bool dup = false;
        for (int j = 0; j < i; j++)
            if (d_csrVp[base + j] == val) { dup = true; break; }
        if (!dup) mine++;
    }
    int distinct = __reduce_add_sync(0xffffffffu, mine);
    float dv = (distinct == 0) ? 1.0f : rsqrtf((float)distinct);

    // gather-sum projected edge rows; lane handles float4 columns lane and lane+32
    float4 accA = make_float4(0.f, 0.f, 0.f, 0.f);
    float4 accB = make_float4(0.f, 0.f, 0.f, 0.f);
    int i = 0;
    for (; i + 2 <= n; i += 2) {
        int e0 = d_csrVp[base + i + 0];
        int e1 = d_csrVp[base + i + 1];
        const float4* r0 = &d_XeP4[(long)e0 * CDIM4];
        const float4* r1 = &d_XeP4[(long)e1 * CDIM4];
        float4 a0 = r0[lane],      a1 = r1[lane];
        float4 b0 = r0[lane + 32], b1 = r1[lane + 32];
        accA.x += a0.x + a1.x; accA.y += a0.y + a1.y;
        accA.z += a0.z + a1.z; accA.w += a0.w + a1.w;
        accB.x += b0.x + b1.x; accB.y += b0.y + b1.y;
        accB.z += b0.z + b1.z; accB.w += b0.w + b1.w;
    }
    for (; i < n; i++) {
        const float4* r = &d_XeP4[(long)d_csrVp[base + i] * CDIM4];
        float4 a = r[lane], b = r[lane + 32];
        accA.x += a.x; accA.y += a.y; accA.z += a.z; accA.w += a.w;
        accB.x += b.x; accB.y += b.y; accB.z += b.z; accB.w += b.w;
    }
    out4[(long)v * CDIM4 + lane]      = make_float4(accA.x*dv, accA.y*dv, accA.z*dv, accA.w*dv);
    out4[(long)v * CDIM4 + lane + 32] = make_float4(accB.x*dv, accB.y*dv, accB.z*dv, accB.w*dv);
}

// -------------------- launch: 5 nodes, one stream, zero events --------------------
extern "C" void kernel_launch(void* const* d_in, const int* in_sizes, int n_in,
                              void* d_out, int out_size)
{
    const float* X      = (const float*)d_in[0];
    const float* W      = (const float*)d_in[1];
    const int*   vertex = (const int*)d_in[2];
    const int*   edges  = (const int*)d_in[3];
    float* out = (float*)d_out;

    int Nv  = in_sizes[0] / CDIM;             // 20000
    int NNZ = in_sizes[2];                    // 160000
    int Me  = (int)((long)in_sizes[4] / Nv);  // 4000
    int nnz4 = NNZ / 4;
    int wn = (Nv + 31) / 32;

    static float *pY = nullptr, *pXeP = nullptr;
    static int *pCur = nullptr;
    if (pY == nullptr) {
        cudaGetSymbolAddress((void**)&pY,   d_Y4);
        cudaGetSymbolAddress((void**)&pXeP, d_XeP4);
        cudaGetSymbolAddress((void**)&pCur, d_cur);
    }

    cudaMemsetAsync(pCur, 0, (size_t)(Me + Nv) * sizeof(int), 0);
    fill_kernel<<<(nnz4 + 255) / 256, 256>>>((const int4*)vertex, (const int4*)edges, nnz4, Me);
    edge_gather_kernel<<<(Me + WPB - 1) / WPB, 32 * WPB>>>((const float4*)X, wn, Me);
    dim3 ggrid((Me + BM - 1) / BM, CDIM / BN);
    sgemm_kernel<<<ggrid, 256>>>(pY, W, pXeP, Me);
    vertex_gather_kernel<<<(Nv + WPB - 1) / WPB, 32 * WPB>>>((float4*)out, Me, Nv);
}